// round 3
// baseline (speedup 1.0000x reference)
#include <cuda_runtime.h>

#define NN 100000
#define IN_DIM 128
#define HID 32
#define ODIM 12
#define MAXE 3400000
#define SCAN_BLK 1024
#define NB_SCAN ((NN + SCAN_BLK - 1) / SCAN_BLK)   // 98

// Scratch (device globals; no allocation allowed)
__device__ __align__(128) float g_h1[NN * HID];      // feat @ W1
__device__ __align__(128) float g_x[NN * HID];       // layer-1 activations
__device__ __align__(128) float g_h2[NN * ODIM];     // x @ W2
__device__ __align__(128) int   g_ssrc[MAXE];        // src sorted by dst
__device__ int g_cnt[NN];
__device__ int g_scanA[NN];
__device__ int g_rowstart[NN + 1];
__device__ int g_cursor[NN];
__device__ int g_bsum[128];
__device__ int g_boff[128];

// ---------------------------------------------------------------------------
__global__ void zero_cnt_kernel() {
    int i = blockIdx.x * blockDim.x + threadIdx.x;
    if (i < NN) g_cnt[i] = 0;
}

// ---------------------------------------------------------------------------
// h1 = feat @ W1   [NN,128] x [128,32] -> [NN,32]
__global__ __launch_bounds__(256) void gemm1_kernel(const float4* __restrict__ feat4,
                                                    const float* __restrict__ W1) {
    __shared__ __align__(16) float fs[64][128];   // 32 KB
    __shared__ __align__(16) float Ws[128][32];   // 16 KB
    int tid = threadIdx.x;
    int base = blockIdx.x * 64;

    for (int i = tid; i < IN_DIM * HID; i += 256)
        ((float*)Ws)[i] = W1[i];

    float4* fs4 = (float4*)fs;
    for (int i = tid; i < 64 * 32; i += 256) {
        int row = i >> 5, c = i & 31;
        int g = base + row;
        fs4[i] = (g < NN) ? feat4[(long long)g * 32 + c]
                          : make_float4(0.f, 0.f, 0.f, 0.f);
    }
    __syncthreads();

    int warp = tid >> 5, lane = tid & 31;
    int r0 = warp * 8;
    float acc[8];
#pragma unroll
    for (int r = 0; r < 8; r++) acc[r] = 0.f;

#pragma unroll 4
    for (int k = 0; k < IN_DIM; k += 4) {
        float w0 = Ws[k + 0][lane];
        float w1 = Ws[k + 1][lane];
        float w2 = Ws[k + 2][lane];
        float w3 = Ws[k + 3][lane];
#pragma unroll
        for (int r = 0; r < 8; r++) {
            float4 f = *(const float4*)&fs[r0 + r][k];
            acc[r] += f.x * w0 + f.y * w1 + f.z * w2 + f.w * w3;
        }
    }
#pragma unroll
    for (int r = 0; r < 8; r++) {
        int g = base + r0 + r;
        if (g < NN) g_h1[(long long)g * HID + lane] = acc[r];
    }
}

// ---------------------------------------------------------------------------
// CSR build: degree histogram
__global__ void hist_kernel(const int* __restrict__ dst, int E) {
    int e = blockIdx.x * blockDim.x + threadIdx.x;
    if (e < E) atomicAdd(&g_cnt[dst[e]], 1);
}

// Scan stage A: per-block inclusive scan of cnt (1024/block)
__global__ __launch_bounds__(SCAN_BLK) void scanA_kernel() {
    __shared__ int s[SCAN_BLK];
    int tid = threadIdx.x;
    int n = blockIdx.x * SCAN_BLK + tid;
    int v = (n < NN) ? g_cnt[n] : 0;
    s[tid] = v;
    __syncthreads();
    for (int off = 1; off < SCAN_BLK; off <<= 1) {
        int t = (tid >= off) ? s[tid - off] : 0;
        __syncthreads();
        if (tid >= off) s[tid] += t;
        __syncthreads();
    }
    if (n < NN) g_scanA[n] = s[tid];
    if (tid == SCAN_BLK - 1) g_bsum[blockIdx.x] = s[tid];
}

// Scan stage B: single block scans block sums -> exclusive block offsets
__global__ __launch_bounds__(128) void scanB_kernel() {
    __shared__ int s[128];
    int tid = threadIdx.x;
    int v = (tid < NB_SCAN) ? g_bsum[tid] : 0;
    s[tid] = v;
    __syncthreads();
    for (int off = 1; off < 128; off <<= 1) {
        int t = (tid >= off) ? s[tid - off] : 0;
        __syncthreads();
        if (tid >= off) s[tid] += t;
        __syncthreads();
    }
    g_boff[tid] = s[tid] - v;  // exclusive
}

// Scan stage C: rowstart (exclusive prefix) + cursor init
__global__ void scanC_kernel(int E) {
    int n = blockIdx.x * blockDim.x + threadIdx.x;
    if (n < NN) {
        int rs = g_boff[n / SCAN_BLK] + g_scanA[n] - g_cnt[n];
        g_rowstart[n] = rs;
        g_cursor[n] = rs;
    }
    if (n == 0) g_rowstart[NN] = E;
}

// Permute: bucket src indices by dst
__global__ void permute_kernel(const int* __restrict__ src,
                               const int* __restrict__ dst, int E) {
    int e = blockIdx.x * blockDim.x + threadIdx.x;
    if (e >= E) return;
    int pos = atomicAdd(&g_cursor[dst[e]], 1);
    g_ssrc[pos] = src[e];
}

// ---------------------------------------------------------------------------
// Gather 1 + finalize: warp per node, lane = column.
// x[n,lane] = relu( (sum_{s in N(n)} h1[s,lane]) / max(deg,1) + b1[lane] )
__global__ __launch_bounds__(256) void gather1_kernel(const float* __restrict__ b1) {
    int w = (blockIdx.x * 256 + threadIdx.x) >> 5;
    int lane = threadIdx.x & 31;
    if (w >= NN) return;
    int e0 = g_rowstart[w];
    int e1 = g_rowstart[w + 1];

    float acc0 = 0.f, acc1 = 0.f, acc2 = 0.f, acc3 = 0.f;
    for (int base = e0; base < e1; base += 32) {
        int idx = base + lane;
        int s = (idx < e1) ? g_ssrc[idx] : 0;
        int m = min(32, e1 - base);
        int j = 0;
        for (; j + 4 <= m; j += 4) {
            int s0 = __shfl_sync(0xffffffffu, s, j + 0);
            int s1 = __shfl_sync(0xffffffffu, s, j + 1);
            int s2 = __shfl_sync(0xffffffffu, s, j + 2);
            int s3 = __shfl_sync(0xffffffffu, s, j + 3);
            float v0 = g_h1[(long long)s0 * HID + lane];
            float v1 = g_h1[(long long)s1 * HID + lane];
            float v2 = g_h1[(long long)s2 * HID + lane];
            float v3 = g_h1[(long long)s3 * HID + lane];
            acc0 += v0; acc1 += v1; acc2 += v2; acc3 += v3;
        }
        for (; j < m; j++) {
            int sj = __shfl_sync(0xffffffffu, s, j);
            acc0 += g_h1[(long long)sj * HID + lane];
        }
    }
    float acc = (acc0 + acc1) + (acc2 + acc3);
    float invd = 1.0f / fmaxf((float)(e1 - e0), 1.0f);
    float x = fmaxf(acc * invd + __ldg(&b1[lane]), 0.f);
    g_x[(long long)w * HID + lane] = x;
}

// ---------------------------------------------------------------------------
// h2 = x @ W2   [NN,32] x [32,12]
__global__ __launch_bounds__(256) void gemm2_kernel(const float* __restrict__ W2) {
    __shared__ float W2s[HID * ODIM];
    int tid = threadIdx.x;
    for (int i = tid; i < HID * ODIM; i += 256) W2s[i] = W2[i];
    __syncthreads();

    int n = blockIdx.x * blockDim.x + tid;
    if (n >= NN) return;

    float acc[ODIM];
#pragma unroll
    for (int j = 0; j < ODIM; j++) acc[j] = 0.f;

    const float4* x4 = (const float4*)g_x + (long long)n * 8;
#pragma unroll
    for (int c4 = 0; c4 < 8; c4++) {
        float4 xv = x4[c4];
        int c = c4 * 4;
#pragma unroll
        for (int j = 0; j < ODIM; j++) {
            acc[j] += xv.x * W2s[(c + 0) * ODIM + j]
                    + xv.y * W2s[(c + 1) * ODIM + j]
                    + xv.z * W2s[(c + 2) * ODIM + j]
                    + xv.w * W2s[(c + 3) * ODIM + j];
        }
    }
    float4* o4 = (float4*)(g_h2 + (long long)n * ODIM);
    o4[0] = make_float4(acc[0], acc[1], acc[2], acc[3]);
    o4[1] = make_float4(acc[4], acc[5], acc[6], acc[7]);
    o4[2] = make_float4(acc[8], acc[9], acc[10], acc[11]);
}

// ---------------------------------------------------------------------------
// Gather 2 + finalize: warp per node; lanes 0-11 accumulate columns.
// out[n,lane] = relu( agg2/deg + b2 )
__global__ __launch_bounds__(256) void gather2_kernel(const float* __restrict__ b2,
                                                      float* __restrict__ out) {
    int w = (blockIdx.x * 256 + threadIdx.x) >> 5;
    int lane = threadIdx.x & 31;
    if (w >= NN) return;
    int e0 = g_rowstart[w];
    int e1 = g_rowstart[w + 1];

    float acc0 = 0.f, acc1 = 0.f;
    bool active = (lane < ODIM);
    for (int base = e0; base < e1; base += 32) {
        int idx = base + lane;
        int s = (idx < e1) ? g_ssrc[idx] : 0;
        int m = min(32, e1 - base);
        int j = 0;
        for (; j + 2 <= m; j += 2) {
            int s0 = __shfl_sync(0xffffffffu, s, j + 0);
            int s1 = __shfl_sync(0xffffffffu, s, j + 1);
            if (active) {
                acc0 += g_h2[(long long)s0 * ODIM + lane];
                acc1 += g_h2[(long long)s1 * ODIM + lane];
            }
        }
        for (; j < m; j++) {
            int sj = __shfl_sync(0xffffffffu, s, j);
            if (active) acc0 += g_h2[(long long)sj * ODIM + lane];
        }
    }
    if (active) {
        float invd = 1.0f / fmaxf((float)(e1 - e0), 1.0f);
        out[(long long)w * ODIM + lane] =
            fmaxf((acc0 + acc1) * invd + __ldg(&b2[lane]), 0.f);
    }
}

// ---------------------------------------------------------------------------
extern "C" void kernel_launch(void* const* d_in, const int* in_sizes, int n_in,
                              void* d_out, int out_size) {
    const float* feat = (const float*)d_in[0];  // [NN,128]
    const int*   src  = (const int*)d_in[1];    // [E]
    const int*   dst  = (const int*)d_in[2];    // [E]
    const float* W1   = (const float*)d_in[3];  // [128,32]
    const float* b1   = (const float*)d_in[4];  // [32]
    const float* W2   = (const float*)d_in[5];  // [32,12]
    const float* b2   = (const float*)d_in[6];  // [12]
    float* out = (float*)d_out;                 // [NN,12]

    int E = in_sizes[1];

    zero_cnt_kernel<<<(NN + 255) / 256, 256>>>();
    gemm1_kernel<<<(NN + 63) / 64, 256>>>((const float4*)feat, W1);
    hist_kernel<<<(E + 255) / 256, 256>>>(dst, E);
    scanA_kernel<<<NB_SCAN, SCAN_BLK>>>();
    scanB_kernel<<<1, 128>>>();
    scanC_kernel<<<(NN + 255) / 256, 256>>>(E);
    permute_kernel<<<(E + 255) / 256, 256>>>(src, dst, E);
    gather1_kernel<<<(NN * 32 + 255) / 256, 256>>>(b1);
    gemm2_kernel<<<(NN + 255) / 256, 256>>>(W2);
    gather2_kernel<<<(NN * 32 + 255) / 256, 256>>>(b2, out);
}

// round 4
// speedup vs baseline: 1.2412x; 1.2412x over previous
#include <cuda_runtime.h>

#define NN 100000
#define IN_DIM 128
#define HID 32
#define ODIM 12
#define MAXE 3400000
#define SCAN_BLK 1024
#define NB_SCAN ((NN + SCAN_BLK - 1) / SCAN_BLK)   // 98

// Scratch (device globals; no allocation allowed)
__device__ __align__(128) float g_h1[NN * HID];      // feat @ W1
__device__ __align__(128) float g_x[NN * HID];       // layer-1 activations
__device__ __align__(128) float g_h2[NN * ODIM];     // x @ W2
__device__ __align__(128) int   g_ssrc[MAXE];        // src sorted by dst
__device__ int g_cnt[NN];
__device__ int g_scanA[NN];
__device__ int g_rowstart[NN + 1];
__device__ int g_cursor[NN];
__device__ int g_bsum[128];
__device__ int g_boff[128];

// ---------------------------------------------------------------------------
__global__ void zero_cnt_kernel() {
    int i = blockIdx.x * blockDim.x + threadIdx.x;
    if (i < NN) g_cnt[i] = 0;
}

// ---------------------------------------------------------------------------
// h1 = feat @ W1   [NN,128] x [128,32] -> [NN,32]
__global__ __launch_bounds__(256) void gemm1_kernel(const float4* __restrict__ feat4,
                                                    const float* __restrict__ W1) {
    __shared__ __align__(16) float fs[64][128];   // 32 KB
    __shared__ __align__(16) float Ws[128][32];   // 16 KB
    int tid = threadIdx.x;
    int base = blockIdx.x * 64;

    for (int i = tid; i < IN_DIM * HID; i += 256)
        ((float*)Ws)[i] = W1[i];

    float4* fs4 = (float4*)fs;
    for (int i = tid; i < 64 * 32; i += 256) {
        int row = i >> 5, c = i & 31;
        int g = base + row;
        fs4[i] = (g < NN) ? feat4[(long long)g * 32 + c]
                          : make_float4(0.f, 0.f, 0.f, 0.f);
    }
    __syncthreads();

    int warp = tid >> 5, lane = tid & 31;
    int r0 = warp * 8;
    float acc[8];
#pragma unroll
    for (int r = 0; r < 8; r++) acc[r] = 0.f;

#pragma unroll 4
    for (int k = 0; k < IN_DIM; k += 4) {
        float w0 = Ws[k + 0][lane];
        float w1 = Ws[k + 1][lane];
        float w2 = Ws[k + 2][lane];
        float w3 = Ws[k + 3][lane];
#pragma unroll
        for (int r = 0; r < 8; r++) {
            float4 f = *(const float4*)&fs[r0 + r][k];
            acc[r] += f.x * w0 + f.y * w1 + f.z * w2 + f.w * w3;
        }
    }
#pragma unroll
    for (int r = 0; r < 8; r++) {
        int g = base + r0 + r;
        if (g < NN) g_h1[(long long)g * HID + lane] = acc[r];
    }
}

// ---------------------------------------------------------------------------
// CSR build: degree histogram (4 edges/thread)
__global__ void hist_kernel(const int4* __restrict__ dst4, int E4, int E,
                            const int* __restrict__ dst) {
    int i = blockIdx.x * blockDim.x + threadIdx.x;
    if (i < E4) {
        int4 d = dst4[i];
        atomicAdd(&g_cnt[d.x], 1);
        atomicAdd(&g_cnt[d.y], 1);
        atomicAdd(&g_cnt[d.z], 1);
        atomicAdd(&g_cnt[d.w], 1);
    }
    int tail = E4 * 4 + i;
    if (i < (E - E4 * 4)) atomicAdd(&g_cnt[dst[tail]], 1);
}

// Scan stage A: per-block inclusive scan of cnt (1024/block)
__global__ __launch_bounds__(SCAN_BLK) void scanA_kernel() {
    __shared__ int s[SCAN_BLK];
    int tid = threadIdx.x;
    int n = blockIdx.x * SCAN_BLK + tid;
    int v = (n < NN) ? g_cnt[n] : 0;
    s[tid] = v;
    __syncthreads();
    for (int off = 1; off < SCAN_BLK; off <<= 1) {
        int t = (tid >= off) ? s[tid - off] : 0;
        __syncthreads();
        if (tid >= off) s[tid] += t;
        __syncthreads();
    }
    if (n < NN) g_scanA[n] = s[tid];
    if (tid == SCAN_BLK - 1) g_bsum[blockIdx.x] = s[tid];
}

// Scan stage B: single block scans block sums -> exclusive block offsets
__global__ __launch_bounds__(128) void scanB_kernel() {
    __shared__ int s[128];
    int tid = threadIdx.x;
    int v = (tid < NB_SCAN) ? g_bsum[tid] : 0;
    s[tid] = v;
    __syncthreads();
    for (int off = 1; off < 128; off <<= 1) {
        int t = (tid >= off) ? s[tid - off] : 0;
        __syncthreads();
        if (tid >= off) s[tid] += t;
        __syncthreads();
    }
    g_boff[tid] = s[tid] - v;  // exclusive
}

// Scan stage C: rowstart (exclusive prefix) + cursor init
__global__ void scanC_kernel(int E) {
    int n = blockIdx.x * blockDim.x + threadIdx.x;
    if (n < NN) {
        int rs = g_boff[n / SCAN_BLK] + g_scanA[n] - g_cnt[n];
        g_rowstart[n] = rs;
        g_cursor[n] = rs;
    }
    if (n == 0) g_rowstart[NN] = E;
}

// Permute: bucket src indices by dst
__global__ void permute_kernel(const int* __restrict__ src,
                               const int* __restrict__ dst, int E) {
    int e = blockIdx.x * blockDim.x + threadIdx.x;
    if (e >= E) return;
    int pos = atomicAdd(&g_cursor[dst[e]], 1);
    g_ssrc[pos] = src[e];
}

// ---------------------------------------------------------------------------
// Gather 1 + finalize. Warp per node. Lane -> (edge-slot lane>>3, colgrp lane&7).
// One LDG.128 warp-instr covers 4 edges' full 128B rows.
__global__ __launch_bounds__(256) void gather1_kernel(const float4* __restrict__ b1v) {
    int w = (blockIdx.x * 256 + threadIdx.x) >> 5;
    int lane = threadIdx.x & 31;
    if (w >= NN) return;
    int e0 = g_rowstart[w];
    int e1 = g_rowstart[w + 1];

    int slot = lane >> 3;     // 0..3 : which edge in the group of 4
    int cg   = lane & 7;      // 0..7 : which float4 of the row
    const float4* h4 = (const float4*)g_h1;

    float a0 = 0.f, a1 = 0.f, a2 = 0.f, a3 = 0.f;
#pragma unroll 4
    for (int base = e0; base < e1; base += 4) {
        int idx = base + slot;
        bool valid = idx < e1;
        int s = valid ? g_ssrc[idx] : 0;
        float4 v = h4[s * 8 + cg];
        if (valid) { a0 += v.x; a1 += v.y; a2 += v.z; a3 += v.w; }
    }
    // reduce over edge-slots: lanes differing in bits 3,4 share colgrp
#pragma unroll
    for (int ofs = 8; ofs <= 16; ofs <<= 1) {
        a0 += __shfl_xor_sync(0xffffffffu, a0, ofs);
        a1 += __shfl_xor_sync(0xffffffffu, a1, ofs);
        a2 += __shfl_xor_sync(0xffffffffu, a2, ofs);
        a3 += __shfl_xor_sync(0xffffffffu, a3, ofs);
    }
    if (lane < 8) {
        float invd = 1.0f / fmaxf((float)(e1 - e0), 1.0f);
        float4 b = __ldg(&b1v[lane]);
        float4 x;
        x.x = fmaxf(a0 * invd + b.x, 0.f);
        x.y = fmaxf(a1 * invd + b.y, 0.f);
        x.z = fmaxf(a2 * invd + b.z, 0.f);
        x.w = fmaxf(a3 * invd + b.w, 0.f);
        ((float4*)g_x)[w * 8 + lane] = x;
    }
}

// ---------------------------------------------------------------------------
// h2 = x @ W2   [NN,32] x [32,12]
__global__ __launch_bounds__(256) void gemm2_kernel(const float* __restrict__ W2) {
    __shared__ float W2s[HID * ODIM];
    int tid = threadIdx.x;
    for (int i = tid; i < HID * ODIM; i += 256) W2s[i] = W2[i];
    __syncthreads();

    int n = blockIdx.x * blockDim.x + tid;
    if (n >= NN) return;

    float acc[ODIM];
#pragma unroll
    for (int j = 0; j < ODIM; j++) acc[j] = 0.f;

    const float4* x4 = (const float4*)g_x + (long long)n * 8;
#pragma unroll
    for (int c4 = 0; c4 < 8; c4++) {
        float4 xv = x4[c4];
        int c = c4 * 4;
#pragma unroll
        for (int j = 0; j < ODIM; j++) {
            acc[j] += xv.x * W2s[(c + 0) * ODIM + j]
                    + xv.y * W2s[(c + 1) * ODIM + j]
                    + xv.z * W2s[(c + 2) * ODIM + j]
                    + xv.w * W2s[(c + 3) * ODIM + j];
        }
    }
    float4* o4 = (float4*)(g_h2 + (long long)n * ODIM);
    o4[0] = make_float4(acc[0], acc[1], acc[2], acc[3]);
    o4[1] = make_float4(acc[4], acc[5], acc[6], acc[7]);
    o4[2] = make_float4(acc[8], acc[9], acc[10], acc[11]);
}

// ---------------------------------------------------------------------------
// Gather 2 + finalize. Warp per node. Lane -> (edge-slot lane>>2, colgrp lane&3).
// Colgrp 3 idle; one LDG.128 warp-instr covers 8 edges' 48B rows.
__global__ __launch_bounds__(256) void gather2_kernel(const float4* __restrict__ b2v,
                                                      float4* __restrict__ out4) {
    int w = (blockIdx.x * 256 + threadIdx.x) >> 5;
    int lane = threadIdx.x & 31;
    if (w >= NN) return;
    int e0 = g_rowstart[w];
    int e1 = g_rowstart[w + 1];

    int slot = lane >> 2;     // 0..7
    int cg   = lane & 3;      // 0..3 (3 idle)
    bool cact = cg < 3;
    const float4* h4 = (const float4*)g_h2;

    float a0 = 0.f, a1 = 0.f, a2 = 0.f, a3 = 0.f;
#pragma unroll 4
    for (int base = e0; base < e1; base += 8) {
        int idx = base + slot;
        bool valid = (idx < e1) && cact;
        int s = (idx < e1) ? g_ssrc[idx] : 0;
        float4 v = h4[s * 3 + (cact ? cg : 0)];
        if (valid) { a0 += v.x; a1 += v.y; a2 += v.z; a3 += v.w; }
    }
    // reduce over edge-slots: lanes differing in bits 2,3,4
#pragma unroll
    for (int ofs = 4; ofs <= 16; ofs <<= 1) {
        a0 += __shfl_xor_sync(0xffffffffu, a0, ofs);
        a1 += __shfl_xor_sync(0xffffffffu, a1, ofs);
        a2 += __shfl_xor_sync(0xffffffffu, a2, ofs);
        a3 += __shfl_xor_sync(0xffffffffu, a3, ofs);
    }
    if (lane < 3) {
        float invd = 1.0f / fmaxf((float)(e1 - e0), 1.0f);
        float4 b = __ldg(&b2v[lane]);
        float4 o;
        o.x = fmaxf(a0 * invd + b.x, 0.f);
        o.y = fmaxf(a1 * invd + b.y, 0.f);
        o.z = fmaxf(a2 * invd + b.z, 0.f);
        o.w = fmaxf(a3 * invd + b.w, 0.f);
        out4[w * 3 + lane] = o;
    }
}

// ---------------------------------------------------------------------------
extern "C" void kernel_launch(void* const* d_in, const int* in_sizes, int n_in,
                              void* d_out, int out_size) {
    const float* feat = (const float*)d_in[0];  // [NN,128]
    const int*   src  = (const int*)d_in[1];    // [E]
    const int*   dst  = (const int*)d_in[2];    // [E]
    const float* W1   = (const float*)d_in[3];  // [128,32]
    const float* b1   = (const float*)d_in[4];  // [32]
    const float* W2   = (const float*)d_in[5];  // [32,12]
    const float* b2   = (const float*)d_in[6];  // [12]
    float* out = (float*)d_out;                 // [NN,12]

    int E = in_sizes[1];
    int E4 = E / 4;

    zero_cnt_kernel<<<(NN + 255) / 256, 256>>>();
    gemm1_kernel<<<(NN + 63) / 64, 256>>>((const float4*)feat, W1);
    hist_kernel<<<(E4 + 255) / 256, 256>>>((const int4*)dst, E4, E, dst);
    scanA_kernel<<<NB_SCAN, SCAN_BLK>>>();
    scanB_kernel<<<1, 128>>>();
    scanC_kernel<<<(NN + 255) / 256, 256>>>(E);
    permute_kernel<<<(E + 255) / 256, 256>>>(src, dst, E);
    gather1_kernel<<<(NN * 32 + 255) / 256, 256>>>((const float4*)b1);
    gemm2_kernel<<<(NN + 255) / 256, 256>>>(W2);
    gather2_kernel<<<(NN * 32 + 255) / 256, 256>>>((const float4*)b2, (float4*)out);
}

// round 6
// speedup vs baseline: 1.2559x; 1.0119x over previous
#include <cuda_runtime.h>
#include <cuda_fp16.h>

#define NN 100000
#define IN_DIM 128
#define HID 32
#define ODIM 12
#define MAXE 3400000
#define SCAN_BLK 1024
#define NB_SCAN ((NN + SCAN_BLK - 1) / SCAN_BLK)   // 98

// Scratch (device globals; no allocation allowed)
__device__ __align__(128) __half g_h1h[NN * HID];    // feat @ W1  (fp16 at rest)
__device__ __align__(128) float  g_x[NN * HID];      // layer-1 activations (fp32)
__device__ __align__(128) __half g_h2h[NN * ODIM];   // x @ W2     (fp16 at rest)
__device__ __align__(128) int    g_ssrc[MAXE];       // src sorted by dst
__device__ int g_cnt[NN];
__device__ int g_scanA[NN];
__device__ int g_rowstart[NN + 1];
__device__ int g_cursor[NN];
__device__ int g_bsum[128];
__device__ int g_boff[128];

// ---------------------------------------------------------------------------
__global__ void zero_cnt_kernel() {
    int i = blockIdx.x * blockDim.x + threadIdx.x;
    if (i < NN) g_cnt[i] = 0;
}

// ---------------------------------------------------------------------------
// h1 = feat @ W1   [NN,128] x [128,32] -> [NN,32], stored fp16
__global__ __launch_bounds__(256) void gemm1_kernel(const float4* __restrict__ feat4,
                                                    const float* __restrict__ W1) {
    __shared__ __align__(16) float fs[64][128];   // 32 KB
    __shared__ __align__(16) float Ws[128][32];   // 16 KB
    int tid = threadIdx.x;
    int base = blockIdx.x * 64;

    for (int i = tid; i < IN_DIM * HID; i += 256)
        ((float*)Ws)[i] = W1[i];

    float4* fs4 = (float4*)fs;
    for (int i = tid; i < 64 * 32; i += 256) {
        int row = i >> 5, c = i & 31;
        int g = base + row;
        fs4[i] = (g < NN) ? feat4[(long long)g * 32 + c]
                          : make_float4(0.f, 0.f, 0.f, 0.f);
    }
    __syncthreads();

    int warp = tid >> 5, lane = tid & 31;
    int r0 = warp * 8;
    float acc[8];
#pragma unroll
    for (int r = 0; r < 8; r++) acc[r] = 0.f;

#pragma unroll 4
    for (int k = 0; k < IN_DIM; k += 4) {
        float w0 = Ws[k + 0][lane];
        float w1 = Ws[k + 1][lane];
        float w2 = Ws[k + 2][lane];
        float w3 = Ws[k + 3][lane];
#pragma unroll
        for (int r = 0; r < 8; r++) {
            float4 f = *(const float4*)&fs[r0 + r][k];
            acc[r] += f.x * w0 + f.y * w1 + f.z * w2 + f.w * w3;
        }
    }
#pragma unroll
    for (int r = 0; r < 8; r++) {
        int g = base + r0 + r;
        if (g < NN) g_h1h[(long long)g * HID + lane] = __float2half_rn(acc[r]);
    }
}

// ---------------------------------------------------------------------------
// CSR build: degree histogram (4 edges/thread)
__global__ void hist_kernel(const int4* __restrict__ dst4, int E4, int E,
                            const int* __restrict__ dst) {
    int i = blockIdx.x * blockDim.x + threadIdx.x;
    if (i < E4) {
        int4 d = dst4[i];
        atomicAdd(&g_cnt[d.x], 1);
        atomicAdd(&g_cnt[d.y], 1);
        atomicAdd(&g_cnt[d.z], 1);
        atomicAdd(&g_cnt[d.w], 1);
    }
    int tail = E4 * 4 + i;
    if (i < (E - E4 * 4)) atomicAdd(&g_cnt[dst[tail]], 1);
}

// Scan stage A: per-block inclusive scan via warp shfl-scan (2 syncs)
__global__ __launch_bounds__(SCAN_BLK) void scanA_kernel() {
    __shared__ int wsum[32];
    int tid = threadIdx.x;
    int lane = tid & 31, wid = tid >> 5;
    int n = blockIdx.x * SCAN_BLK + tid;
    int x = (n < NN) ? g_cnt[n] : 0;
#pragma unroll
    for (int o = 1; o < 32; o <<= 1) {
        int t = __shfl_up_sync(0xffffffffu, x, o);
        if (lane >= o) x += t;
    }
    if (lane == 31) wsum[wid] = x;
    __syncthreads();
    if (wid == 0) {
        int s = wsum[lane];
#pragma unroll
        for (int o = 1; o < 32; o <<= 1) {
            int t = __shfl_up_sync(0xffffffffu, s, o);
            if (lane >= o) s += t;
        }
        wsum[lane] = s;
    }
    __syncthreads();
    if (wid > 0) x += wsum[wid - 1];
    if (n < NN) g_scanA[n] = x;
    if (tid == SCAN_BLK - 1) g_bsum[blockIdx.x] = x;
}

// Scan stage B: single block scans block sums -> exclusive block offsets
__global__ __launch_bounds__(128) void scanB_kernel() {
    __shared__ int s[128];
    int tid = threadIdx.x;
    int v = (tid < NB_SCAN) ? g_bsum[tid] : 0;
    s[tid] = v;
    __syncthreads();
    for (int off = 1; off < 128; off <<= 1) {
        int t = (tid >= off) ? s[tid - off] : 0;
        __syncthreads();
        if (tid >= off) s[tid] += t;
        __syncthreads();
    }
    g_boff[tid] = s[tid] - v;  // exclusive
}

// Scan stage C: rowstart (exclusive prefix) + cursor init
__global__ void scanC_kernel(int E) {
    int n = blockIdx.x * blockDim.x + threadIdx.x;
    if (n < NN) {
        int rs = g_boff[n / SCAN_BLK] + g_scanA[n] - g_cnt[n];
        g_rowstart[n] = rs;
        g_cursor[n] = rs;
    }
    if (n == 0) g_rowstart[NN] = E;
}

// Permute: bucket src indices by dst (4 edges/thread)
__global__ void permute_kernel(const int4* __restrict__ src4,
                               const int4* __restrict__ dst4, int E4, int E,
                               const int* __restrict__ src,
                               const int* __restrict__ dst) {
    int i = blockIdx.x * blockDim.x + threadIdx.x;
    if (i < E4) {
        int4 s = src4[i];
        int4 d = dst4[i];
        g_ssrc[atomicAdd(&g_cursor[d.x], 1)] = s.x;
        g_ssrc[atomicAdd(&g_cursor[d.y], 1)] = s.y;
        g_ssrc[atomicAdd(&g_cursor[d.z], 1)] = s.z;
        g_ssrc[atomicAdd(&g_cursor[d.w], 1)] = s.w;
    }
    int tail = E4 * 4 + i;
    if (i < (E - E4 * 4))
        g_ssrc[atomicAdd(&g_cursor[dst[tail]], 1)] = src[tail];
}

// ---------------------------------------------------------------------------
// Gather 1 + finalize. Warp per node. Lane -> (edge-slot lane>>2, colgrp lane&3).
// fp16 rows (64B): one LDG.128 warp-instr covers 8 edges' full rows.
__global__ __launch_bounds__(256) void gather1_kernel(const float4* __restrict__ b1v) {
    int w = (blockIdx.x * 256 + threadIdx.x) >> 5;
    int lane = threadIdx.x & 31;
    if (w >= NN) return;
    int e0 = g_rowstart[w];
    int e1 = g_rowstart[w + 1];

    int slot = lane >> 2;     // 0..7 : edge within group of 8
    int cg   = lane & 3;      // 0..3 : which float4 (8 halves) of the 64B row
    const float4* h4 = (const float4*)g_h1h;

    float a0 = 0.f, a1 = 0.f, a2 = 0.f, a3 = 0.f;
    float a4 = 0.f, a5 = 0.f, a6 = 0.f, a7 = 0.f;
#pragma unroll 2
    for (int base = e0; base < e1; base += 8) {
        int idx = base + slot;
        bool valid = idx < e1;
        int s = valid ? __ldg(&g_ssrc[idx]) : 0;
        float4 v = h4[s * 4 + cg];
        if (valid) {
            const __half2* hp = (const __half2*)&v;
            float2 f;
            f = __half22float2(hp[0]); a0 += f.x; a1 += f.y;
            f = __half22float2(hp[1]); a2 += f.x; a3 += f.y;
            f = __half22float2(hp[2]); a4 += f.x; a5 += f.y;
            f = __half22float2(hp[3]); a6 += f.x; a7 += f.y;
        }
    }
    // reduce over edge-slots (lane bits 2,3,4)
#pragma unroll
    for (int ofs = 4; ofs <= 16; ofs <<= 1) {
        a0 += __shfl_xor_sync(0xffffffffu, a0, ofs);
        a1 += __shfl_xor_sync(0xffffffffu, a1, ofs);
        a2 += __shfl_xor_sync(0xffffffffu, a2, ofs);
        a3 += __shfl_xor_sync(0xffffffffu, a3, ofs);
        a4 += __shfl_xor_sync(0xffffffffu, a4, ofs);
        a5 += __shfl_xor_sync(0xffffffffu, a5, ofs);
        a6 += __shfl_xor_sync(0xffffffffu, a6, ofs);
        a7 += __shfl_xor_sync(0xffffffffu, a7, ofs);
    }
    if (lane < 4) {   // lane == cg, slot 0: owns columns cg*8 .. cg*8+7
        float invd = 1.0f / fmaxf((float)(e1 - e0), 1.0f);
        float4 bA = __ldg(&b1v[lane * 2 + 0]);
        float4 bB = __ldg(&b1v[lane * 2 + 1]);
        float4 xA, xB;
        xA.x = fmaxf(a0 * invd + bA.x, 0.f);
        xA.y = fmaxf(a1 * invd + bA.y, 0.f);
        xA.z = fmaxf(a2 * invd + bA.z, 0.f);
        xA.w = fmaxf(a3 * invd + bA.w, 0.f);
        xB.x = fmaxf(a4 * invd + bB.x, 0.f);
        xB.y = fmaxf(a5 * invd + bB.y, 0.f);
        xB.z = fmaxf(a6 * invd + bB.z, 0.f);
        xB.w = fmaxf(a7 * invd + bB.w, 0.f);
        ((float4*)g_x)[w * 8 + lane * 2 + 0] = xA;
        ((float4*)g_x)[w * 8 + lane * 2 + 1] = xB;
    }
}

// ---------------------------------------------------------------------------
// h2 = x @ W2   [NN,32] x [32,12], stored fp16 (24B rows)
__global__ __launch_bounds__(256) void gemm2_kernel(const float* __restrict__ W2) {
    __shared__ float W2s[HID * ODIM];
    int tid = threadIdx.x;
    for (int i = tid; i < HID * ODIM; i += 256) W2s[i] = W2[i];
    __syncthreads();

    int n = blockIdx.x * blockDim.x + tid;
    if (n >= NN) return;

    float acc[ODIM];
#pragma unroll
    for (int j = 0; j < ODIM; j++) acc[j] = 0.f;

    const float4* x4 = (const float4*)g_x + (long long)n * 8;
#pragma unroll
    for (int c4 = 0; c4 < 8; c4++) {
        float4 xv = x4[c4];
        int c = c4 * 4;
#pragma unroll
        for (int j = 0; j < ODIM; j++) {
            acc[j] += xv.x * W2s[(c + 0) * ODIM + j]
                    + xv.y * W2s[(c + 1) * ODIM + j]
                    + xv.z * W2s[(c + 2) * ODIM + j]
                    + xv.w * W2s[(c + 3) * ODIM + j];
        }
    }
    uint2 u0, u1, u2;
    ((__half2*)&u0)[0] = __floats2half2_rn(acc[0], acc[1]);
    ((__half2*)&u0)[1] = __floats2half2_rn(acc[2], acc[3]);
    ((__half2*)&u1)[0] = __floats2half2_rn(acc[4], acc[5]);
    ((__half2*)&u1)[1] = __floats2half2_rn(acc[6], acc[7]);
    ((__half2*)&u2)[0] = __floats2half2_rn(acc[8], acc[9]);
    ((__half2*)&u2)[1] = __floats2half2_rn(acc[10], acc[11]);
    uint2* o = (uint2*)(g_h2h + (long long)n * ODIM);
    o[0] = u0; o[1] = u1; o[2] = u2;
}

// ---------------------------------------------------------------------------
// Gather 2 + finalize. Warp per node. fp16 rows (24B = 3x uint2).
// Lane -> (edge-slot lane>>2, colgrp lane&3, grp 3 idle): 8 edges per LDG.64.
__global__ __launch_bounds__(256) void gather2_kernel(const float4* __restrict__ b2v,
                                                      float4* __restrict__ out4) {
    int w = (blockIdx.x * 256 + threadIdx.x) >> 5;
    int lane = threadIdx.x & 31;
    if (w >= NN) return;
    int e0 = g_rowstart[w];
    int e1 = g_rowstart[w + 1];

    int slot = lane >> 2;     // 0..7
    int cg   = lane & 3;      // 0..3 (3 idle)
    bool cact = cg < 3;
    const uint2* hp = (const uint2*)g_h2h;

    float a0 = 0.f, a1 = 0.f, a2 = 0.f, a3 = 0.f;
#pragma unroll 2
    for (int base = e0; base < e1; base += 8) {
        int idx = base + slot;
        bool valid = idx < e1;
        int s = valid ? __ldg(&g_ssrc[idx]) : 0;
        uint2 d = hp[s * 3 + (cact ? cg : 0)];
        if (valid && cact) {
            float2 f;
            f = __half22float2(*(const __half2*)&d.x); a0 += f.x; a1 += f.y;
            f = __half22float2(*(const __half2*)&d.y); a2 += f.x; a3 += f.y;
        }
    }
#pragma unroll
    for (int ofs = 4; ofs <= 16; ofs <<= 1) {
        a0 += __shfl_xor_sync(0xffffffffu, a0, ofs);
        a1 += __shfl_xor_sync(0xffffffffu, a1, ofs);
        a2 += __shfl_xor_sync(0xffffffffu, a2, ofs);
        a3 += __shfl_xor_sync(0xffffffffu, a3, ofs);
    }
    if (lane < 3) {   // lane == cg: owns columns cg*4 .. cg*4+3
        float invd = 1.0f / fmaxf((float)(e1 - e0), 1.0f);
        float4 b = __ldg(&b2v[lane]);
        float4 o;
        o.x = fmaxf(a0 * invd + b.x, 0.f);
        o.y = fmaxf(a1 * invd + b.y, 0.f);
        o.z = fmaxf(a2 * invd + b.z, 0.f);
        o.w = fmaxf(a3 * invd + b.w, 0.f);
        out4[w * 3 + lane] = o;
    }
}

// ---------------------------------------------------------------------------
extern "C" void kernel_launch(void* const* d_in, const int* in_sizes, int n_in,
                              void* d_out, int out_size) {
    const float* feat = (const float*)d_in[0];  // [NN,128]
    const int*   src  = (const int*)d_in[1];    // [E]
    const int*   dst  = (const int*)d_in[2];    // [E]
    const float* W1   = (const float*)d_in[3];  // [128,32]
    const float* b1   = (const float*)d_in[4];  // [32]
    const float* W2   = (const float*)d_in[5];  // [32,12]
    const float* b2   = (const float*)d_in[6];  // [12]
    float* out = (float*)d_out;                 // [NN,12]

    int E = in_sizes[1];
    int E4 = E / 4;

    zero_cnt_kernel<<<(NN + 255) / 256, 256>>>();
    gemm1_kernel<<<(NN + 63) / 64, 256>>>((const float4*)feat, W1);
    hist_kernel<<<(E4 + 255) / 256, 256>>>((const int4*)dst, E4, E, dst);
    scanA_kernel<<<NB_SCAN, SCAN_BLK>>>();
    scanB_kernel<<<1, 128>>>();
    scanC_kernel<<<(NN + 255) / 256, 256>>>(E);
    permute_kernel<<<(E4 + 255) / 256, 256>>>((const int4*)src, (const int4*)dst,
                                              E4, E, src, dst);
    gather1_kernel<<<(NN * 32 + 255) / 256, 256>>>((const float4*)b1);
    gemm2_kernel<<<(NN + 255) / 256, 256>>>(W2);
    gather2_kernel<<<(NN * 32 + 255) / 256, 256>>>((const float4*)b2, (float4*)out);
}

// round 7
// speedup vs baseline: 1.2659x; 1.0080x over previous
#include <cuda_runtime.h>
#include <cuda_fp16.h>

#define NN 100000
#define IN_DIM 128
#define HID 32
#define ODIM 12
#define MAXE 3400000
#define SCAN_EPB 4096                              // elements per scan block
#define NB_SCAN ((NN + SCAN_EPB - 1) / SCAN_EPB)   // 25

// Scratch (device globals; no allocation allowed)
__device__ __align__(128) __half g_h1h[NN * HID];    // feat @ W1  (fp16 at rest)
__device__ __align__(128) float  g_x[NN * HID];      // layer-1 activations (fp32)
__device__ __align__(128) __half g_h2h[NN * ODIM];   // x @ W2     (fp16 at rest)
__device__ __align__(128) int    g_ssrc[MAXE];       // src sorted by dst
__device__ __align__(16) int g_cnt[NN];
__device__ __align__(16) int g_scanA[NN];
__device__ int g_rowstart[NN + 1];
__device__ int g_cursor[NN];
__device__ int g_bsum[128];
__device__ int g_boff[128];

// ---------------------------------------------------------------------------
__global__ void zero_cnt_kernel() {
    int i = blockIdx.x * blockDim.x + threadIdx.x;
    if (i < NN) g_cnt[i] = 0;
}

// ---------------------------------------------------------------------------
// h1 = feat @ W1   [NN,128] x [128,32] -> [NN,32], stored fp16
__global__ __launch_bounds__(256) void gemm1_kernel(const float4* __restrict__ feat4,
                                                    const float* __restrict__ W1) {
    __shared__ __align__(16) float fs[64][128];   // 32 KB
    __shared__ __align__(16) float Ws[128][32];   // 16 KB
    int tid = threadIdx.x;
    int base = blockIdx.x * 64;

    for (int i = tid; i < IN_DIM * HID; i += 256)
        ((float*)Ws)[i] = W1[i];

    float4* fs4 = (float4*)fs;
    for (int i = tid; i < 64 * 32; i += 256) {
        int row = i >> 5, c = i & 31;
        int g = base + row;
        fs4[i] = (g < NN) ? feat4[(long long)g * 32 + c]
                          : make_float4(0.f, 0.f, 0.f, 0.f);
    }
    __syncthreads();

    int warp = tid >> 5, lane = tid & 31;
    int r0 = warp * 8;
    float acc[8];
#pragma unroll
    for (int r = 0; r < 8; r++) acc[r] = 0.f;

#pragma unroll 4
    for (int k = 0; k < IN_DIM; k += 4) {
        float w0 = Ws[k + 0][lane];
        float w1 = Ws[k + 1][lane];
        float w2 = Ws[k + 2][lane];
        float w3 = Ws[k + 3][lane];
#pragma unroll
        for (int r = 0; r < 8; r++) {
            float4 f = *(const float4*)&fs[r0 + r][k];
            acc[r] += f.x * w0 + f.y * w1 + f.z * w2 + f.w * w3;
        }
    }
#pragma unroll
    for (int r = 0; r < 8; r++) {
        int g = base + r0 + r;
        if (g < NN) g_h1h[(long long)g * HID + lane] = __float2half_rn(acc[r]);
    }
}

// ---------------------------------------------------------------------------
// CSR build: degree histogram (4 edges/thread)
__global__ void hist_kernel(const int4* __restrict__ dst4, int E4, int E,
                            const int* __restrict__ dst) {
    int i = blockIdx.x * blockDim.x + threadIdx.x;
    if (i < E4) {
        int4 d = dst4[i];
        atomicAdd(&g_cnt[d.x], 1);
        atomicAdd(&g_cnt[d.y], 1);
        atomicAdd(&g_cnt[d.z], 1);
        atomicAdd(&g_cnt[d.w], 1);
    }
    int tail = E4 * 4 + i;
    if (i < (E - E4 * 4)) atomicAdd(&g_cnt[dst[tail]], 1);
}

// Scan stage A: 4 elems/thread (int4) + warp shfl-scan. 25 blocks x 1024 thr.
__global__ __launch_bounds__(1024) void scanA_kernel() {
    __shared__ int wsum[32];
    int tid = threadIdx.x, lane = tid & 31, wid = tid >> 5;
    int i4 = blockIdx.x * 1024 + tid;
    const int N4 = NN / 4;  // 25000
    int4 c = (i4 < N4) ? ((const int4*)g_cnt)[i4] : make_int4(0, 0, 0, 0);
    int l0 = c.x;
    int l1 = l0 + c.y;
    int l2 = l1 + c.z;
    int l3 = l2 + c.w;
    int x = l3;
#pragma unroll
    for (int o = 1; o < 32; o <<= 1) {
        int t = __shfl_up_sync(0xffffffffu, x, o);
        if (lane >= o) x += t;
    }
    if (lane == 31) wsum[wid] = x;
    __syncthreads();
    if (wid == 0) {
        int s = wsum[lane];
#pragma unroll
        for (int o = 1; o < 32; o <<= 1) {
            int t = __shfl_up_sync(0xffffffffu, s, o);
            if (lane >= o) s += t;
        }
        wsum[lane] = s;
    }
    __syncthreads();
    int add = (wid > 0 ? wsum[wid - 1] : 0) + (x - l3);  // exclusive-of-this-thread
    if (i4 < N4) {
        int4 o;
        o.x = l0 + add; o.y = l1 + add; o.z = l2 + add; o.w = l3 + add;
        ((int4*)g_scanA)[i4] = o;
    }
    if (tid == 1023) g_bsum[blockIdx.x] = wsum[31];
}

// Scan stage B: single block scans block sums -> exclusive block offsets
__global__ __launch_bounds__(128) void scanB_kernel() {
    __shared__ int s[128];
    int tid = threadIdx.x;
    int v = (tid < NB_SCAN) ? g_bsum[tid] : 0;
    s[tid] = v;
    __syncthreads();
    for (int off = 1; off < 128; off <<= 1) {
        int t = (tid >= off) ? s[tid - off] : 0;
        __syncthreads();
        if (tid >= off) s[tid] += t;
        __syncthreads();
    }
    g_boff[tid] = s[tid] - v;  // exclusive
}

// Scan stage C: rowstart (exclusive prefix) + cursor init
__global__ void scanC_kernel(int E) {
    int n = blockIdx.x * blockDim.x + threadIdx.x;
    if (n < NN) {
        int rs = g_boff[n / SCAN_EPB] + g_scanA[n] - g_cnt[n];
        g_rowstart[n] = rs;
        g_cursor[n] = rs;
    }
    if (n == 0) g_rowstart[NN] = E;
}

// Permute: bucket src indices by dst (4 edges/thread)
__global__ void permute_kernel(const int4* __restrict__ src4,
                               const int4* __restrict__ dst4, int E4, int E,
                               const int* __restrict__ src,
                               const int* __restrict__ dst) {
    int i = blockIdx.x * blockDim.x + threadIdx.x;
    if (i < E4) {
        int4 s = src4[i];
        int4 d = dst4[i];
        g_ssrc[atomicAdd(&g_cursor[d.x], 1)] = s.x;
        g_ssrc[atomicAdd(&g_cursor[d.y], 1)] = s.y;
        g_ssrc[atomicAdd(&g_cursor[d.z], 1)] = s.z;
        g_ssrc[atomicAdd(&g_cursor[d.w], 1)] = s.w;
    }
    int tail = E4 * 4 + i;
    if (i < (E - E4 * 4))
        g_ssrc[atomicAdd(&g_cursor[dst[tail]], 1)] = src[tail];
}

// ---------------------------------------------------------------------------
// Gather 1 + finalize. Warp per node. Lane -> (edge-slot lane>>2, colgrp lane&3).
// Index prefetch: next iteration's ssrc load issues before this iteration's
// h1 row load, collapsing the serial ssrc->row chain. unroll 4 => 4 row loads
// in flight per warp.
__global__ __launch_bounds__(256) void gather1_kernel(const float4* __restrict__ b1v) {
    int w = (blockIdx.x * 256 + threadIdx.x) >> 5;
    int lane = threadIdx.x & 31;
    if (w >= NN) return;
    int e0 = __ldg(&g_rowstart[w]);
    int e1 = __ldg(&g_rowstart[w + 1]);

    int slot = lane >> 2;     // 0..7 : edge within group of 8
    int cg   = lane & 3;      // 0..3 : which float4 (8 halves) of the 64B row
    const float4* h4 = (const float4*)g_h1h;

    float a0 = 0.f, a1 = 0.f, a2 = 0.f, a3 = 0.f;
    float a4 = 0.f, a5 = 0.f, a6 = 0.f, a7 = 0.f;

    int idx = e0 + slot;
    bool val = idx < e1;
    int s = val ? __ldg(&g_ssrc[idx]) : 0;
#pragma unroll 4
    for (int base = e0; base < e1; base += 8) {
        int nidx = base + 8 + slot;
        bool nval = nidx < e1;
        int ns = nval ? __ldg(&g_ssrc[nidx]) : 0;   // prefetch next group
        float4 v = __ldg(&h4[s * 4 + cg]);
        if (val) {
            const __half2* hp = (const __half2*)&v;
            float2 f;
            f = __half22float2(hp[0]); a0 += f.x; a1 += f.y;
            f = __half22float2(hp[1]); a2 += f.x; a3 += f.y;
            f = __half22float2(hp[2]); a4 += f.x; a5 += f.y;
            f = __half22float2(hp[3]); a6 += f.x; a7 += f.y;
        }
        s = ns; val = nval;
    }
    // reduce over edge-slots (lane bits 2,3,4)
#pragma unroll
    for (int ofs = 4; ofs <= 16; ofs <<= 1) {
        a0 += __shfl_xor_sync(0xffffffffu, a0, ofs);
        a1 += __shfl_xor_sync(0xffffffffu, a1, ofs);
        a2 += __shfl_xor_sync(0xffffffffu, a2, ofs);
        a3 += __shfl_xor_sync(0xffffffffu, a3, ofs);
        a4 += __shfl_xor_sync(0xffffffffu, a4, ofs);
        a5 += __shfl_xor_sync(0xffffffffu, a5, ofs);
        a6 += __shfl_xor_sync(0xffffffffu, a6, ofs);
        a7 += __shfl_xor_sync(0xffffffffu, a7, ofs);
    }
    if (lane < 4) {   // lane == cg, slot 0: owns columns cg*8 .. cg*8+7
        float invd = 1.0f / fmaxf((float)(e1 - e0), 1.0f);
        float4 bA = __ldg(&b1v[lane * 2 + 0]);
        float4 bB = __ldg(&b1v[lane * 2 + 1]);
        float4 xA, xB;
        xA.x = fmaxf(a0 * invd + bA.x, 0.f);
        xA.y = fmaxf(a1 * invd + bA.y, 0.f);
        xA.z = fmaxf(a2 * invd + bA.z, 0.f);
        xA.w = fmaxf(a3 * invd + bA.w, 0.f);
        xB.x = fmaxf(a4 * invd + bB.x, 0.f);
        xB.y = fmaxf(a5 * invd + bB.y, 0.f);
        xB.z = fmaxf(a6 * invd + bB.z, 0.f);
        xB.w = fmaxf(a7 * invd + bB.w, 0.f);
        ((float4*)g_x)[w * 8 + lane * 2 + 0] = xA;
        ((float4*)g_x)[w * 8 + lane * 2 + 1] = xB;
    }
}

// ---------------------------------------------------------------------------
// h2 = x @ W2   [NN,32] x [32,12], stored fp16 (24B rows)
__global__ __launch_bounds__(256) void gemm2_kernel(const float* __restrict__ W2) {
    __shared__ float W2s[HID * ODIM];
    int tid = threadIdx.x;
    for (int i = tid; i < HID * ODIM; i += 256) W2s[i] = W2[i];
    __syncthreads();

    int n = blockIdx.x * blockDim.x + tid;
    if (n >= NN) return;

    float acc[ODIM];
#pragma unroll
    for (int j = 0; j < ODIM; j++) acc[j] = 0.f;

    const float4* x4 = (const float4*)g_x + (long long)n * 8;
#pragma unroll
    for (int c4 = 0; c4 < 8; c4++) {
        float4 xv = x4[c4];
        int c = c4 * 4;
#pragma unroll
        for (int j = 0; j < ODIM; j++) {
            acc[j] += xv.x * W2s[(c + 0) * ODIM + j]
                    + xv.y * W2s[(c + 1) * ODIM + j]
                    + xv.z * W2s[(c + 2) * ODIM + j]
                    + xv.w * W2s[(c + 3) * ODIM + j];
        }
    }
    uint2 u0, u1, u2;
    ((__half2*)&u0)[0] = __floats2half2_rn(acc[0], acc[1]);
    ((__half2*)&u0)[1] = __floats2half2_rn(acc[2], acc[3]);
    ((__half2*)&u1)[0] = __floats2half2_rn(acc[4], acc[5]);
    ((__half2*)&u1)[1] = __floats2half2_rn(acc[6], acc[7]);
    ((__half2*)&u2)[0] = __floats2half2_rn(acc[8], acc[9]);
    ((__half2*)&u2)[1] = __floats2half2_rn(acc[10], acc[11]);
    uint2* o = (uint2*)(g_h2h + (long long)n * ODIM);
    o[0] = u0; o[1] = u1; o[2] = u2;
}

// ---------------------------------------------------------------------------
// Gather 2 + finalize. Warp per node. fp16 rows (24B = 3x uint2).
// Same index-prefetch pipeline; 8 edges per LDG.64 warp-instr.
__global__ __launch_bounds__(256) void gather2_kernel(const float4* __restrict__ b2v,
                                                      float4* __restrict__ out4) {
    int w = (blockIdx.x * 256 + threadIdx.x) >> 5;
    int lane = threadIdx.x & 31;
    if (w >= NN) return;
    int e0 = __ldg(&g_rowstart[w]);
    int e1 = __ldg(&g_rowstart[w + 1]);

    int slot = lane >> 2;     // 0..7
    int cg   = lane & 3;      // 0..3 (3 idle)
    bool cact = cg < 3;
    const uint2* hp = (const uint2*)g_h2h;
    int coff = cact ? cg : 0;

    float a0 = 0.f, a1 = 0.f, a2 = 0.f, a3 = 0.f;

    int idx = e0 + slot;
    bool val = idx < e1;
    int s = val ? __ldg(&g_ssrc[idx]) : 0;
#pragma unroll 4
    for (int base = e0; base < e1; base += 8) {
        int nidx = base + 8 + slot;
        bool nval = nidx < e1;
        int ns = nval ? __ldg(&g_ssrc[nidx]) : 0;
        uint2 d = __ldg(&hp[s * 3 + coff]);
        if (val && cact) {
            float2 f;
            f = __half22float2(*(const __half2*)&d.x); a0 += f.x; a1 += f.y;
            f = __half22float2(*(const __half2*)&d.y); a2 += f.x; a3 += f.y;
        }
        s = ns; val = nval;
    }
#pragma unroll
    for (int ofs = 4; ofs <= 16; ofs <<= 1) {
        a0 += __shfl_xor_sync(0xffffffffu, a0, ofs);
        a1 += __shfl_xor_sync(0xffffffffu, a1, ofs);
        a2 += __shfl_xor_sync(0xffffffffu, a2, ofs);
        a3 += __shfl_xor_sync(0xffffffffu, a3, ofs);
    }
    if (lane < 3) {   // lane == cg: owns columns cg*4 .. cg*4+3
        float invd = 1.0f / fmaxf((float)(e1 - e0), 1.0f);
        float4 b = __ldg(&b2v[lane]);
        float4 o;
        o.x = fmaxf(a0 * invd + b.x, 0.f);
        o.y = fmaxf(a1 * invd + b.y, 0.f);
        o.z = fmaxf(a2 * invd + b.z, 0.f);
        o.w = fmaxf(a3 * invd + b.w, 0.f);
        out4[w * 3 + lane] = o;
    }
}

// ---------------------------------------------------------------------------
extern "C" void kernel_launch(void* const* d_in, const int* in_sizes, int n_in,
                              void* d_out, int out_size) {
    const float* feat = (const float*)d_in[0];  // [NN,128]
    const int*   src  = (const int*)d_in[1];    // [E]
    const int*   dst  = (const int*)d_in[2];    // [E]
    const float* W1   = (const float*)d_in[3];  // [128,32]
    const float* b1   = (const float*)d_in[4];  // [32]
    const float* W2   = (const float*)d_in[5];  // [32,12]
    const float* b2   = (const float*)d_in[6];  // [12]
    float* out = (float*)d_out;                 // [NN,12]

    int E = in_sizes[1];
    int E4 = E / 4;

    zero_cnt_kernel<<<(NN + 255) / 256, 256>>>();
    gemm1_kernel<<<(NN + 63) / 64, 256>>>((const float4*)feat, W1);
    hist_kernel<<<(E4 + 255) / 256, 256>>>((const int4*)dst, E4, E, dst);
    scanA_kernel<<<NB_SCAN, 1024>>>();
    scanB_kernel<<<1, 128>>>();
    scanC_kernel<<<(NN + 255) / 256, 256>>>(E);
    permute_kernel<<<(E4 + 255) / 256, 256>>>((const int4*)src, (const int4*)dst,
                                              E4, E, src, dst);
    gather1_kernel<<<(NN * 32 + 255) / 256, 256>>>((const float4*)b1);
    gemm2_kernel<<<(NN + 255) / 256, 256>>>(W2);
    gather2_kernel<<<(NN * 32 + 255) / 256, 256>>>((const float4*)b2, (float4*)out);
}

// round 8
// speedup vs baseline: 1.2835x; 1.0139x over previous
#include <cuda_runtime.h>
#include <cuda_fp16.h>

#define NN 100000
#define IN_DIM 128
#define HID 32
#define ODIM 12
#define MAXE 3400000
#define SCAN_EPB 4096                              // elements per scanA block
#define NB_SCAN ((NN + SCAN_EPB - 1) / SCAN_EPB)   // 25

// Scratch (device globals; no allocation allowed). g_cnt relies on static
// zero-init for the first call; scanC re-zeroes it for every subsequent call.
__device__ __align__(128) __half g_h1h[NN * HID];    // feat @ W1  (fp16 at rest)
__device__ __align__(128) float  g_x[NN * HID];      // layer-1 activations (fp32)
__device__ __align__(128) __half g_h2h[NN * ODIM];   // x @ W2     (fp16 at rest)
__device__ __align__(128) int    g_ssrc[MAXE];       // src sorted by dst
__device__ __align__(16) int g_cnt[NN];
__device__ __align__(16) int g_scanA[NN];            // exclusive-within-block
__device__ int g_rowstart[NN + 1];
__device__ int g_cursor[NN];
__device__ int g_bsum[32];

#define ADD_F32X2(out, a, b) \
    asm("add.rn.f32x2 %0, %1, %2;" : "=l"(out) : "l"(a), "l"(b))

__device__ __forceinline__ unsigned long long pack_f2(float2 f) {
    unsigned long long t;
    asm("mov.b64 %0, {%1, %2};" : "=l"(t) : "f"(f.x), "f"(f.y));
    return t;
}

// ---------------------------------------------------------------------------
// CSR build: degree histogram (4 edges/thread). Assumes g_cnt is zero
// (static init on call 1; scanC zeroes it at the end of every call).
__global__ void hist_kernel(const int4* __restrict__ dst4, int E4, int E,
                            const int* __restrict__ dst) {
    int i = blockIdx.x * blockDim.x + threadIdx.x;
    if (i < E4) {
        int4 d = dst4[i];
        atomicAdd(&g_cnt[d.x], 1);
        atomicAdd(&g_cnt[d.y], 1);
        atomicAdd(&g_cnt[d.z], 1);
        atomicAdd(&g_cnt[d.w], 1);
    }
    int tail = E4 * 4 + i;
    if (i < (E - E4 * 4)) atomicAdd(&g_cnt[dst[tail]], 1);
}

// Scan stage A: 4 elems/thread (int4), EXCLUSIVE-within-block output.
__global__ __launch_bounds__(1024) void scanA_kernel() {
    __shared__ int wsum[32];
    int tid = threadIdx.x, lane = tid & 31, wid = tid >> 5;
    int i4 = blockIdx.x * 1024 + tid;
    const int N4 = NN / 4;  // 25000
    int4 c = (i4 < N4) ? ((const int4*)g_cnt)[i4] : make_int4(0, 0, 0, 0);
    int l0 = c.x;
    int l1 = l0 + c.y;
    int l2 = l1 + c.z;
    int l3 = l2 + c.w;
    int x = l3;
#pragma unroll
    for (int o = 1; o < 32; o <<= 1) {
        int t = __shfl_up_sync(0xffffffffu, x, o);
        if (lane >= o) x += t;
    }
    if (lane == 31) wsum[wid] = x;
    __syncthreads();
    if (wid == 0) {
        int s = wsum[lane];
#pragma unroll
        for (int o = 1; o < 32; o <<= 1) {
            int t = __shfl_up_sync(0xffffffffu, s, o);
            if (lane >= o) s += t;
        }
        wsum[lane] = s;
    }
    __syncthreads();
    int add = (wid > 0 ? wsum[wid - 1] : 0) + (x - l3);  // exclusive of this thread
    if (i4 < N4) {
        int4 o;
        o.x = add; o.y = add + l0; o.z = add + l1; o.w = add + l2;
        ((int4*)g_scanA)[i4] = o;
    }
    if (tid == 1023) g_bsum[blockIdx.x] = wsum[31];
}

// Scan stage C (scanB inlined): every block shfl-scans the 25 block sums,
// then computes rowstart/cursor; also re-zeroes g_cnt for the next call.
__global__ __launch_bounds__(256) void scanC_kernel(int E) {
    __shared__ int boff[32];
    int tid = threadIdx.x;
    if (tid < 32) {
        int v = (tid < NB_SCAN) ? g_bsum[tid] : 0;
        int x = v;
#pragma unroll
        for (int o = 1; o < 32; o <<= 1) {
            int t = __shfl_up_sync(0xffffffffu, x, o);
            if (tid >= o) x += t;
        }
        boff[tid] = x - v;  // exclusive
    }
    __syncthreads();
    int n = blockIdx.x * 256 + tid;
    if (n < NN) {
        int rs = boff[n >> 12] + g_scanA[n];   // SCAN_EPB = 4096 = 1<<12
        g_rowstart[n] = rs;
        g_cursor[n] = rs;
        g_cnt[n] = 0;                          // clean for next call's hist
    }
    if (n == 0) g_rowstart[NN] = E;
}

// ---------------------------------------------------------------------------
// h1 = feat @ W1   [NN,128] x [128,32] -> [NN,32], stored fp16
__global__ __launch_bounds__(256) void gemm1_kernel(const float4* __restrict__ feat4,
                                                    const float* __restrict__ W1) {
    __shared__ __align__(16) float fs[64][128];   // 32 KB
    __shared__ __align__(16) float Ws[128][32];   // 16 KB
    int tid = threadIdx.x;
    int base = blockIdx.x * 64;

    for (int i = tid; i < IN_DIM * HID; i += 256)
        ((float*)Ws)[i] = W1[i];

    float4* fs4 = (float4*)fs;
    for (int i = tid; i < 64 * 32; i += 256) {
        int row = i >> 5, c = i & 31;
        int g = base + row;
        fs4[i] = (g < NN) ? feat4[(long long)g * 32 + c]
                          : make_float4(0.f, 0.f, 0.f, 0.f);
    }
    __syncthreads();

    int warp = tid >> 5, lane = tid & 31;
    int r0 = warp * 8;
    float acc[8];
#pragma unroll
    for (int r = 0; r < 8; r++) acc[r] = 0.f;

#pragma unroll 4
    for (int k = 0; k < IN_DIM; k += 4) {
        float w0 = Ws[k + 0][lane];
        float w1 = Ws[k + 1][lane];
        float w2 = Ws[k + 2][lane];
        float w3 = Ws[k + 3][lane];
#pragma unroll
        for (int r = 0; r < 8; r++) {
            float4 f = *(const float4*)&fs[r0 + r][k];
            acc[r] += f.x * w0 + f.y * w1 + f.z * w2 + f.w * w3;
        }
    }
#pragma unroll
    for (int r = 0; r < 8; r++) {
        int g = base + r0 + r;
        if (g < NN) g_h1h[(long long)g * HID + lane] = __float2half_rn(acc[r]);
    }
}

// ---------------------------------------------------------------------------
// Permute: bucket src indices by dst (4 edges/thread)
__global__ void permute_kernel(const int4* __restrict__ src4,
                               const int4* __restrict__ dst4, int E4, int E,
                               const int* __restrict__ src,
                               const int* __restrict__ dst) {
    int i = blockIdx.x * blockDim.x + threadIdx.x;
    if (i < E4) {
        int4 s = src4[i];
        int4 d = dst4[i];
        g_ssrc[atomicAdd(&g_cursor[d.x], 1)] = s.x;
        g_ssrc[atomicAdd(&g_cursor[d.y], 1)] = s.y;
        g_ssrc[atomicAdd(&g_cursor[d.z], 1)] = s.z;
        g_ssrc[atomicAdd(&g_cursor[d.w], 1)] = s.w;
    }
    int tail = E4 * 4 + i;
    if (i < (E - E4 * 4))
        g_ssrc[atomicAdd(&g_cursor[dst[tail]], 1)] = src[tail];
}

// ---------------------------------------------------------------------------
// Gather 1 + finalize. Warp per node. Lane -> (edge-slot lane>>2, colgrp lane&3).
// Index prefetch + packed f32x2 accumulation.
__global__ __launch_bounds__(256) void gather1_kernel(const float4* __restrict__ b1v) {
    int w = (blockIdx.x * 256 + threadIdx.x) >> 5;
    int lane = threadIdx.x & 31;
    if (w >= NN) return;
    int e0 = __ldg(&g_rowstart[w]);
    int e1 = __ldg(&g_rowstart[w + 1]);

    int slot = lane >> 2;     // 0..7 : edge within group of 8
    int cg   = lane & 3;      // 0..3 : which float4 (8 halves) of the 64B row
    const float4* h4 = (const float4*)g_h1h;

    unsigned long long A0 = 0ull, A1 = 0ull, A2 = 0ull, A3 = 0ull;

    int idx = e0 + slot;
    bool val = idx < e1;
    int s = val ? __ldg(&g_ssrc[idx]) : 0;
#pragma unroll 4
    for (int base = e0; base < e1; base += 8) {
        int nidx = base + 8 + slot;
        bool nval = nidx < e1;
        int ns = nval ? __ldg(&g_ssrc[nidx]) : 0;   // prefetch next group
        float4 v = __ldg(&h4[s * 4 + cg]);
        if (val) {
            const __half2* hp = (const __half2*)&v;
            ADD_F32X2(A0, A0, pack_f2(__half22float2(hp[0])));
            ADD_F32X2(A1, A1, pack_f2(__half22float2(hp[1])));
            ADD_F32X2(A2, A2, pack_f2(__half22float2(hp[2])));
            ADD_F32X2(A3, A3, pack_f2(__half22float2(hp[3])));
        }
        s = ns; val = nval;
    }
    float2 f0 = *(float2*)&A0, f1 = *(float2*)&A1;
    float2 f2 = *(float2*)&A2, f3 = *(float2*)&A3;
    float a0 = f0.x, a1 = f0.y, a2 = f1.x, a3 = f1.y;
    float a4 = f2.x, a5 = f2.y, a6 = f3.x, a7 = f3.y;
    // reduce over edge-slots (lane bits 2,3,4)
#pragma unroll
    for (int ofs = 4; ofs <= 16; ofs <<= 1) {
        a0 += __shfl_xor_sync(0xffffffffu, a0, ofs);
        a1 += __shfl_xor_sync(0xffffffffu, a1, ofs);
        a2 += __shfl_xor_sync(0xffffffffu, a2, ofs);
        a3 += __shfl_xor_sync(0xffffffffu, a3, ofs);
        a4 += __shfl_xor_sync(0xffffffffu, a4, ofs);
        a5 += __shfl_xor_sync(0xffffffffu, a5, ofs);
        a6 += __shfl_xor_sync(0xffffffffu, a6, ofs);
        a7 += __shfl_xor_sync(0xffffffffu, a7, ofs);
    }
    if (lane < 4) {   // lane == cg, slot 0: owns columns cg*8 .. cg*8+7
        float invd = 1.0f / fmaxf((float)(e1 - e0), 1.0f);
        float4 bA = __ldg(&b1v[lane * 2 + 0]);
        float4 bB = __ldg(&b1v[lane * 2 + 1]);
        float4 xA, xB;
        xA.x = fmaxf(a0 * invd + bA.x, 0.f);
        xA.y = fmaxf(a1 * invd + bA.y, 0.f);
        xA.z = fmaxf(a2 * invd + bA.z, 0.f);
        xA.w = fmaxf(a3 * invd + bA.w, 0.f);
        xB.x = fmaxf(a4 * invd + bB.x, 0.f);
        xB.y = fmaxf(a5 * invd + bB.y, 0.f);
        xB.z = fmaxf(a6 * invd + bB.z, 0.f);
        xB.w = fmaxf(a7 * invd + bB.w, 0.f);
        ((float4*)g_x)[w * 8 + lane * 2 + 0] = xA;
        ((float4*)g_x)[w * 8 + lane * 2 + 1] = xB;
    }
}

// ---------------------------------------------------------------------------
// h2 = x @ W2   [NN,32] x [32,12], stored fp16 (24B rows)
__global__ __launch_bounds__(256) void gemm2_kernel(const float* __restrict__ W2) {
    __shared__ float W2s[HID * ODIM];
    int tid = threadIdx.x;
    for (int i = tid; i < HID * ODIM; i += 256) W2s[i] = W2[i];
    __syncthreads();

    int n = blockIdx.x * blockDim.x + tid;
    if (n >= NN) return;

    float acc[ODIM];
#pragma unroll
    for (int j = 0; j < ODIM; j++) acc[j] = 0.f;

    const float4* x4 = (const float4*)g_x + (long long)n * 8;
#pragma unroll
    for (int c4 = 0; c4 < 8; c4++) {
        float4 xv = x4[c4];
        int c = c4 * 4;
#pragma unroll
        for (int j = 0; j < ODIM; j++) {
            acc[j] += xv.x * W2s[(c + 0) * ODIM + j]
                    + xv.y * W2s[(c + 1) * ODIM + j]
                    + xv.z * W2s[(c + 2) * ODIM + j]
                    + xv.w * W2s[(c + 3) * ODIM + j];
        }
    }
    uint2 u0, u1, u2;
    ((__half2*)&u0)[0] = __floats2half2_rn(acc[0], acc[1]);
    ((__half2*)&u0)[1] = __floats2half2_rn(acc[2], acc[3]);
    ((__half2*)&u1)[0] = __floats2half2_rn(acc[4], acc[5]);
    ((__half2*)&u1)[1] = __floats2half2_rn(acc[6], acc[7]);
    ((__half2*)&u2)[0] = __floats2half2_rn(acc[8], acc[9]);
    ((__half2*)&u2)[1] = __floats2half2_rn(acc[10], acc[11]);
    uint2* o = (uint2*)(g_h2h + (long long)n * ODIM);
    o[0] = u0; o[1] = u1; o[2] = u2;
}

// ---------------------------------------------------------------------------
// Gather 2 + finalize. Warp per node. fp16 rows (24B = 3x uint2).
// Index prefetch + packed f32x2 accumulation; 8 edges per LDG.64 warp-instr.
__global__ __launch_bounds__(256) void gather2_kernel(const float4* __restrict__ b2v,
                                                      float4* __restrict__ out4) {
    int w = (blockIdx.x * 256 + threadIdx.x) >> 5;
    int lane = threadIdx.x & 31;
    if (w >= NN) return;
    int e0 = __ldg(&g_rowstart[w]);
    int e1 = __ldg(&g_rowstart[w + 1]);

    int slot = lane >> 2;     // 0..7
    int cg   = lane & 3;      // 0..3 (3 idle)
    bool cact = cg < 3;
    const uint2* hp = (const uint2*)g_h2h;
    int coff = cact ? cg : 0;

    unsigned long long A0 = 0ull, A1 = 0ull;

    int idx = e0 + slot;
    bool val = idx < e1;
    int s = val ? __ldg(&g_ssrc[idx]) : 0;
#pragma unroll 4
    for (int base = e0; base < e1; base += 8) {
        int nidx = base + 8 + slot;
        bool nval = nidx < e1;
        int ns = nval ? __ldg(&g_ssrc[nidx]) : 0;
        uint2 d = __ldg(&hp[s * 3 + coff]);
        if (val && cact) {
            ADD_F32X2(A0, A0, pack_f2(__half22float2(*(const __half2*)&d.x)));
            ADD_F32X2(A1, A1, pack_f2(__half22float2(*(const __half2*)&d.y)));
        }
        s = ns; val = nval;
    }
    float2 f0 = *(float2*)&A0, f1 = *(float2*)&A1;
    float a0 = f0.x, a1 = f0.y, a2 = f1.x, a3 = f1.y;
#pragma unroll
    for (int ofs = 4; ofs <= 16; ofs <<= 1) {
        a0 += __shfl_xor_sync(0xffffffffu, a0, ofs);
        a1 += __shfl_xor_sync(0xffffffffu, a1, ofs);
        a2 += __shfl_xor_sync(0xffffffffu, a2, ofs);
        a3 += __shfl_xor_sync(0xffffffffu, a3, ofs);
    }
    if (lane < 3) {   // lane == cg: owns columns cg*4 .. cg*4+3
        float invd = 1.0f / fmaxf((float)(e1 - e0), 1.0f);
        float4 b = __ldg(&b2v[lane]);
        float4 o;
        o.x = fmaxf(a0 * invd + b.x, 0.f);
        o.y = fmaxf(a1 * invd + b.y, 0.f);
        o.z = fmaxf(a2 * invd + b.z, 0.f);
        o.w = fmaxf(a3 * invd + b.w, 0.f);
        out4[w * 3 + lane] = o;
    }
}

// ---------------------------------------------------------------------------
extern "C" void kernel_launch(void* const* d_in, const int* in_sizes, int n_in,
                              void* d_out, int out_size) {
    const float* feat = (const float*)d_in[0];  // [NN,128]
    const int*   src  = (const int*)d_in[1];    // [E]
    const int*   dst  = (const int*)d_in[2];    // [E]
    const float* W1   = (const float*)d_in[3];  // [128,32]
    const float* b1   = (const float*)d_in[4];  // [32]
    const float* W2   = (const float*)d_in[5];  // [32,12]
    const float* b2   = (const float*)d_in[6];  // [12]
    float* out = (float*)d_out;                 // [NN,12]

    int E = in_sizes[1];
    int E4 = E / 4;

    // Launch index 3 = gemm1 (ncu captures idx 3 -> real profile next round)
    hist_kernel<<<(E4 + 255) / 256, 256>>>((const int4*)dst, E4, E, dst);      // 0
    scanA_kernel<<<NB_SCAN, 1024>>>();                                          // 1
    scanC_kernel<<<(NN + 255) / 256, 256>>>(E);                                 // 2
    gemm1_kernel<<<(NN + 63) / 64, 256>>>((const float4*)feat, W1);             // 3
    permute_kernel<<<(E4 + 255) / 256, 256>>>((const int4*)src, (const int4*)dst,
                                              E4, E, src, dst);                 // 4
    gather1_kernel<<<(NN * 32 + 255) / 256, 256>>>((const float4*)b1);          // 5
    gemm2_kernel<<<(NN + 255) / 256, 256>>>(W2);                                // 6
    gather2_kernel<<<(NN * 32 + 255) / 256, 256>>>((const float4*)b2,
                                                   (float4*)out);               // 7
}